// round 14
// baseline (speedup 1.0000x reference)
#include <cuda_runtime.h>
#include <cuda_fp16.h>
#include <math.h>

// ---------------------------------------------------------------------------
// SphereDistanceField: hash-grid encode (fp32) + fully-fused HMMA MLP.
// R12 = R11 with the level-0 shared cache sized CORRECTLY: dense corner
// indices reach ix+1 + (iy+1)*16 + (iz+1)*256 = 4368 (coords hit 16 at the
// upper edge), so we stage 4384 entries, not 4096. R11's 4096-entry copy
// caused OOB shared reads -> illegal memory access.
// Base config = R9 (79 regs / 3 CTAs, 787us proven).
// ---------------------------------------------------------------------------

#define NLEV 16
#define TSIZE (1u << 19)
#define TMASK (TSIZE - 1u)
#define PRIME1 2654435761u
#define PRIME2 805459861u

#define BLOCK 256
#define L0N   4384                     // >= 4369 = max dense idx + 1, 16-aligned

// shared layout (bytes)
#define WS1_OFF 0                      // W1^T fp16 [64][72]   = 9216 B
#define WS2_OFF 9216                   // W2^T fp16 [64][72]   = 9216 B
#define B1S_OFF 18432                  // b1 fp32 [64]
#define B2S_OFF (B1S_OFF + 256)
#define W3S_OFF (B2S_OFF + 256)
#define B3S_OFF (W3S_OFF + 256)
#define X_OFF   19456                  // X fp16 [256][72]; H1 ALIASES X
#define L0S_OFF (X_OFF + 36864)        // level-0 table fp16x2 [L0N] = 17536 B
#define SMEM_BYTES (L0S_OFF + L0N * 4) // 73856 B -> 3 CTAs/SM (221.6 KB)

struct Scales { float s[NLEV]; };

__device__ __forceinline__ void mma16816(float& c0, float& c1, float& c2, float& c3,
                                         unsigned a0, unsigned a1, unsigned a2, unsigned a3,
                                         unsigned b0, unsigned b1) {
    asm volatile("mma.sync.aligned.m16n8k16.row.col.f32.f16.f16.f32 "
                 "{%0,%1,%2,%3}, {%4,%5,%6,%7}, {%8,%9}, {%0,%1,%2,%3};"
                 : "+f"(c0), "+f"(c1), "+f"(c2), "+f"(c3)
                 : "r"(a0), "r"(a1), "r"(a2), "r"(a3), "r"(b0), "r"(b1));
}

__global__ __launch_bounds__(BLOCK, 3)
void sdf_kernel(const float* __restrict__ dirs,
                const float* __restrict__ table,
                const float* __restrict__ W1, const float* __restrict__ b1,
                const float* __restrict__ W2, const float* __restrict__ b2,
                const float* __restrict__ W3, const float* __restrict__ b3,
                float* __restrict__ out, int n, Scales sc)
{
    extern __shared__ __align__(16) char smem[];
    __half*  ws1h = (__half*)(smem + WS1_OFF);
    __half*  ws2h = (__half*)(smem + WS2_OFF);
    float*   b1s  = (float*)(smem + B1S_OFF);
    float*   b2s  = (float*)(smem + B2S_OFF);
    float*   w3s  = (float*)(smem + W3S_OFF);
    float*   b3s  = (float*)(smem + B3S_OFF);
    __half2* l0h  = (__half2*)(smem + L0S_OFF);

    const int tid = threadIdx.x;

    // ---- stage weights (transposed, fp16) + level-0 table ----
    for (int i = tid; i < 64 * 72 / 2; i += BLOCK)
        ((unsigned*)ws1h)[i] = 0u;
    __syncthreads();
    for (int i = tid; i < 35 * 64; i += BLOCK) {
        int k = i >> 6, nn = i & 63;
        ws1h[nn * 72 + k] = __float2half(W1[i]);
    }
    for (int i = tid; i < 64 * 64; i += BLOCK) {
        int k = i >> 6, nn = i & 63;
        ws2h[nn * 72 + k] = __float2half(W2[i]);
    }
    {
        const float2* t0 = reinterpret_cast<const float2*>(table);
        for (int i = tid; i < L0N; i += BLOCK) {
            const float2 v = t0[i];
            l0h[i] = __floats2half2_rn(v.x, v.y);
        }
    }
    if (tid < 64) {
        b1s[tid] = b1[tid];
        b2s[tid] = b2[tid];
        w3s[tid] = W3[tid];
        if (tid == 0) b3s[0] = b3[0];
    }
    __syncthreads();

    // ---- encode (one thread = one ray) ----
    const int ray  = blockIdx.x * BLOCK + tid;
    const int rayc = ray < n ? ray : (n - 1);

    const float dx = dirs[rayc * 3 + 0];
    const float dy = dirs[rayc * 3 + 1];
    const float dz = dirs[rayc * 3 + 2];
    const float x = fmaf(dx, 0.49f, 0.49f);
    const float y = fmaf(dy, 0.49f, 0.49f);
    const float z = fmaf(dz, 0.49f, 0.49f);

    __half2* Xh2 = (__half2*)(smem + X_OFF);
    const int xrow = tid * 36;

    Xh2[xrow + 0] = __floats2half2_rn(dx, dy);
    float prev = dz;

    // ---- level 0: dense 16^3 from SHARED (fp16) ----
    {
        const float s = sc.s[0];
        const float px = fmaf(x, s, 0.5f);
        const float py = fmaf(y, s, 0.5f);
        const float pz = fmaf(z, s, 0.5f);
        const float fpx = floorf(px), fpy = floorf(py), fpz = floorf(pz);
        const float fx = px - fpx, fy = py - fpy, fz = pz - fpz;
        const unsigned ix = (unsigned)fpx, iy = (unsigned)fpy, iz = (unsigned)fpz;
        const float wx = fx * fx * (3.0f - 2.0f * fx);
        const float wy = fy * fy * (3.0f - 2.0f * fy);
        const float wz = fz * fz * (3.0f - 2.0f * fz);
        const float wx0 = 1.0f - wx, wy0 = 1.0f - wy, wz0 = 1.0f - wz;

        const unsigned base = ix + iy * 16u + iz * 256u;
        const float2 c0 = __half22float2(l0h[base]);
        const float2 c1 = __half22float2(l0h[base + 1u]);
        const float2 c2 = __half22float2(l0h[base + 16u]);
        const float2 c3 = __half22float2(l0h[base + 17u]);
        const float2 c4 = __half22float2(l0h[base + 256u]);
        const float2 c5 = __half22float2(l0h[base + 257u]);
        const float2 c6 = __half22float2(l0h[base + 272u]);
        const float2 c7 = __half22float2(l0h[base + 273u]);

        const float w00 = wx0 * wy0, w10 = wx * wy0;
        const float w01 = wx0 * wy,  w11 = wx * wy;

        float t0 = c0.x * w00;  t0 = fmaf(c1.x, w10, t0);
        t0 = fmaf(c2.x, w01, t0); t0 = fmaf(c3.x, w11, t0);
        float t1 = c4.x * w00;  t1 = fmaf(c5.x, w10, t1);
        t1 = fmaf(c6.x, w01, t1); t1 = fmaf(c7.x, w11, t1);
        const float a0 = fmaf(t1, wz, t0 * wz0);

        float u0 = c0.y * w00;  u0 = fmaf(c1.y, w10, u0);
        u0 = fmaf(c2.y, w01, u0); u0 = fmaf(c3.y, w11, u0);
        float u1 = c4.y * w00;  u1 = fmaf(c5.y, w10, u1);
        u1 = fmaf(c6.y, w01, u1); u1 = fmaf(c7.y, w11, u1);
        const float a1 = fmaf(u1, wz, u0 * wz0);

        Xh2[xrow + 1] = __floats2half2_rn(prev, a0);
        prev = a1;
    }

    // ---- dense levels 1..4 from GLOBAL, unrolled ----
    const unsigned RES[4] = {23u, 31u, 43u, 59u};
    #pragma unroll
    for (int l = 1; l < 5; l++) {
        const float s = sc.s[l];
        const float px = fmaf(x, s, 0.5f);
        const float py = fmaf(y, s, 0.5f);
        const float pz = fmaf(z, s, 0.5f);
        const float fpx = floorf(px), fpy = floorf(py), fpz = floorf(pz);
        const float fx = px - fpx, fy = py - fpy, fz = pz - fpz;
        const unsigned ix = (unsigned)fpx, iy = (unsigned)fpy, iz = (unsigned)fpz;
        const float wx = fx * fx * (3.0f - 2.0f * fx);
        const float wy = fy * fy * (3.0f - 2.0f * fy);
        const float wz = fz * fz * (3.0f - 2.0f * fz);
        const float wx0 = 1.0f - wx, wy0 = 1.0f - wy, wz0 = 1.0f - wz;

        const unsigned R = RES[l - 1], R2 = R * R;
        const unsigned base = ix + iy * R + iz * R2;

        const float2* tl = reinterpret_cast<const float2*>(table) + (size_t)l * TSIZE;
        const float2 c0 = tl[base];           const float2 c1 = tl[base + 1u];
        const float2 c2 = tl[base + R];       const float2 c3 = tl[base + R + 1u];
        const float2 c4 = tl[base + R2];      const float2 c5 = tl[base + R2 + 1u];
        const float2 c6 = tl[base + R2 + R];  const float2 c7 = tl[base + R2 + R + 1u];

        const float w00 = wx0 * wy0, w10 = wx * wy0;
        const float w01 = wx0 * wy,  w11 = wx * wy;

        float t0 = c0.x * w00;  t0 = fmaf(c1.x, w10, t0);
        t0 = fmaf(c2.x, w01, t0); t0 = fmaf(c3.x, w11, t0);
        float t1 = c4.x * w00;  t1 = fmaf(c5.x, w10, t1);
        t1 = fmaf(c6.x, w01, t1); t1 = fmaf(c7.x, w11, t1);
        const float a0 = fmaf(t1, wz, t0 * wz0);

        float u0 = c0.y * w00;  u0 = fmaf(c1.y, w10, u0);
        u0 = fmaf(c2.y, w01, u0); u0 = fmaf(c3.y, w11, u0);
        float u1 = c4.y * w00;  u1 = fmaf(c5.y, w10, u1);
        u1 = fmaf(c6.y, w01, u1); u1 = fmaf(c7.y, w11, u1);
        const float a1 = fmaf(u1, wz, u0 * wz0);

        Xh2[xrow + l + 1] = __floats2half2_rn(prev, a0);
        prev = a1;
    }

    // ---- hashed levels 5..15, rolled ----
    #pragma unroll 1
    for (int l = 5; l < NLEV; l++) {
        const float s = sc.s[l];
        const float px = fmaf(x, s, 0.5f);
        const float py = fmaf(y, s, 0.5f);
        const float pz = fmaf(z, s, 0.5f);
        const float fpx = floorf(px), fpy = floorf(py), fpz = floorf(pz);
        const float fx = px - fpx, fy = py - fpy, fz = pz - fpz;
        const unsigned ix = (unsigned)fpx, iy = (unsigned)fpy, iz = (unsigned)fpz;
        const float wx = fx * fx * (3.0f - 2.0f * fx);
        const float wy = fy * fy * (3.0f - 2.0f * fy);
        const float wz = fz * fz * (3.0f - 2.0f * fz);
        const float wx0 = 1.0f - wx, wy0 = 1.0f - wy, wz0 = 1.0f - wz;

        const unsigned hx0 = ix,          hx1 = ix + 1u;
        const unsigned hy0 = iy * PRIME1, hy1 = hy0 + PRIME1;
        const unsigned hz0 = iz * PRIME2, hz1 = hz0 + PRIME2;
        const unsigned idx0 = (hx0 ^ hy0 ^ hz0) & TMASK;
        const unsigned idx1 = (hx1 ^ hy0 ^ hz0) & TMASK;
        const unsigned idx2 = (hx0 ^ hy1 ^ hz0) & TMASK;
        const unsigned idx3 = (hx1 ^ hy1 ^ hz0) & TMASK;
        const unsigned idx4 = (hx0 ^ hy0 ^ hz1) & TMASK;
        const unsigned idx5 = (hx1 ^ hy0 ^ hz1) & TMASK;
        const unsigned idx6 = (hx0 ^ hy1 ^ hz1) & TMASK;
        const unsigned idx7 = (hx1 ^ hy1 ^ hz1) & TMASK;

        const float2* tl = reinterpret_cast<const float2*>(table) + (size_t)l * TSIZE;
        const float2 c0 = tl[idx0], c1 = tl[idx1], c2 = tl[idx2], c3 = tl[idx3];
        const float2 c4 = tl[idx4], c5 = tl[idx5], c6 = tl[idx6], c7 = tl[idx7];

        const float w00 = wx0 * wy0, w10 = wx * wy0;
        const float w01 = wx0 * wy,  w11 = wx * wy;

        float t0 = c0.x * w00;  t0 = fmaf(c1.x, w10, t0);
        t0 = fmaf(c2.x, w01, t0); t0 = fmaf(c3.x, w11, t0);
        float t1 = c4.x * w00;  t1 = fmaf(c5.x, w10, t1);
        t1 = fmaf(c6.x, w01, t1); t1 = fmaf(c7.x, w11, t1);
        const float a0 = fmaf(t1, wz, t0 * wz0);

        float u0 = c0.y * w00;  u0 = fmaf(c1.y, w10, u0);
        u0 = fmaf(c2.y, w01, u0); u0 = fmaf(c3.y, w11, u0);
        float u1 = c4.y * w00;  u1 = fmaf(c5.y, w10, u1);
        u1 = fmaf(c6.y, w01, u1); u1 = fmaf(c7.y, w11, u1);
        const float a1 = fmaf(u1, wz, u0 * wz0);

        Xh2[xrow + l + 1] = __floats2half2_rn(prev, a0);
        prev = a1;
    }
    Xh2[xrow + 17] = __floats2half2_rn(prev, 0.0f);
    const __half2 zero2 = __floats2half2_rn(0.0f, 0.0f);
    #pragma unroll
    for (int p = 18; p < 24; p++) Xh2[xrow + p] = zero2;

    __syncwarp();

    // ---- fused MLP: one warp = 32 rays; H1 aliases X ----
    const int lane = tid & 31;
    const int warp = tid >> 5;
    const int g   = lane >> 2;
    const int tig = lane & 3;
    const int wbase = warp * 32;

    const unsigned* Xu  = (const unsigned*)(smem + X_OFF);
    const unsigned* W1u = (const unsigned*)ws1h;
    const unsigned* W2u = (const unsigned*)ws2h;
    __half2*        H1h = (__half2*)(smem + X_OFF);     // alias
    const unsigned* H1u = (const unsigned*)H1h;

    // ---- layer 1: [32,48] @ [48,64] ----
    #pragma unroll
    for (int mt = 0; mt < 2; mt++) {
        const int r0 = wbase + mt * 16 + g;
        unsigned a[3][4];
        #pragma unroll
        for (int kt = 0; kt < 3; kt++) {
            const int o = r0 * 36 + kt * 8 + tig;
            a[kt][0] = Xu[o];           a[kt][1] = Xu[o + 288];
            a[kt][2] = Xu[o + 4];       a[kt][3] = Xu[o + 292];
        }
        #pragma unroll
        for (int nt = 0; nt < 8; nt++) {
            float c0 = 0.f, c1 = 0.f, c2 = 0.f, c3 = 0.f;
            #pragma unroll
            for (int kt = 0; kt < 3; kt++) {
                const int bo = (nt * 8 + g) * 36 + kt * 8 + tig;
                mma16816(c0, c1, c2, c3, a[kt][0], a[kt][1], a[kt][2], a[kt][3],
                         W1u[bo], W1u[bo + 4]);
            }
            const float2 bb = *(const float2*)&b1s[nt * 8 + tig * 2];
            const int ho = r0 * 36 + nt * 4 + tig;
            H1h[ho]       = __floats2half2_rn(fmaxf(c0 + bb.x, 0.f), fmaxf(c1 + bb.y, 0.f));
            H1h[ho + 288] = __floats2half2_rn(fmaxf(c2 + bb.x, 0.f), fmaxf(c3 + bb.y, 0.f));
        }
    }
    __syncwarp();

    // ---- layer 2 + fused layer 3 ----
    const float b3v = b3s[0];
    #pragma unroll
    for (int mt = 0; mt < 2; mt++) {
        const int r0 = wbase + mt * 16 + g;
        unsigned a[4][4];
        #pragma unroll
        for (int kt = 0; kt < 4; kt++) {
            const int o = r0 * 36 + kt * 8 + tig;
            a[kt][0] = H1u[o];          a[kt][1] = H1u[o + 288];
            a[kt][2] = H1u[o + 4];      a[kt][3] = H1u[o + 292];
        }
        float p0 = 0.f, p1 = 0.f;
        #pragma unroll
        for (int nt = 0; nt < 8; nt++) {
            float c0 = 0.f, c1 = 0.f, c2 = 0.f, c3 = 0.f;
            #pragma unroll
            for (int kt = 0; kt < 4; kt++) {
                const int bo = (nt * 8 + g) * 36 + kt * 8 + tig;
                mma16816(c0, c1, c2, c3, a[kt][0], a[kt][1], a[kt][2], a[kt][3],
                         W2u[bo], W2u[bo + 4]);
            }
            const float2 bb  = *(const float2*)&b2s[nt * 8 + tig * 2];
            const float2 w3v = *(const float2*)&w3s[nt * 8 + tig * 2];
            p0 = fmaf(fmaxf(c0 + bb.x, 0.f), w3v.x, p0);
            p0 = fmaf(fmaxf(c1 + bb.y, 0.f), w3v.y, p0);
            p1 = fmaf(fmaxf(c2 + bb.x, 0.f), w3v.x, p1);
            p1 = fmaf(fmaxf(c3 + bb.y, 0.f), w3v.y, p1);
        }
        p0 += __shfl_xor_sync(0xFFFFFFFFu, p0, 1);
        p0 += __shfl_xor_sync(0xFFFFFFFFu, p0, 2);
        p1 += __shfl_xor_sync(0xFFFFFFFFu, p1, 1);
        p1 += __shfl_xor_sync(0xFFFFFFFFu, p1, 2);

        if (tig == 0) {
            const int rbase = blockIdx.x * BLOCK + wbase + mt * 16 + g;
            {
                const float xv = p0 + b3v + 1.0f;
                if (rbase < n)
                    out[rbase] = fmaxf(xv, 0.0f) + log1pf(expf(-fabsf(xv)));
            }
            {
                const float xv = p1 + b3v + 1.0f;
                if (rbase + 8 < n)
                    out[rbase + 8] = fmaxf(xv, 0.0f) + log1pf(expf(-fabsf(xv)));
            }
        }
    }
}

extern "C" void kernel_launch(void* const* d_in, const int* in_sizes, int n_in,
                              void* d_out, int out_size) {
    const float* dirs  = (const float*)d_in[0];
    const float* table = (const float*)d_in[1];
    const float* W1 = (const float*)d_in[2];
    const float* b1 = (const float*)d_in[3];
    const float* W2 = (const float*)d_in[4];
    const float* b2 = (const float*)d_in[5];
    const float* W3 = (const float*)d_in[6];
    const float* b3 = (const float*)d_in[7];
    float* out = (float*)d_out;

    const int n = in_sizes[0] / 3;

    Scales sc;
    const double PLS = exp(log(2048.0 / 16.0) / 15.0);
    for (int l = 0; l < NLEV; l++)
        sc.s[l] = (float)(16.0 * pow(PLS, (double)l) - 1.0);

    cudaFuncSetAttribute(sdf_kernel, cudaFuncAttributeMaxDynamicSharedMemorySize,
                         SMEM_BYTES);

    const int blocks = (n + BLOCK - 1) / BLOCK;
    sdf_kernel<<<blocks, BLOCK, SMEM_BYTES>>>(dirs, table, W1, b1, W2, b2, W3, b3,
                                              out, n, sc);
}

// round 17
// speedup vs baseline: 1.9859x; 1.9859x over previous
#include <cuda_runtime.h>
#include <cuda_fp16.h>
#include <math.h>

// ---------------------------------------------------------------------------
// SphereDistanceField: hash-grid encode (fp32) + fully-fused HMMA MLP.
// R14 = R9 (787us proven: dense 0-4 unrolled from global, hashed 5-15 rolled,
// H1 aliases X, plain C++ deref loads) with ONE knob: BLOCK 256 -> 384 at
// 2 CTAs/SM. Same 24 warps/SM, but smem/SM 169 -> 149.5 KB, so the L1D
// carveout grows 59 -> 79 KB (R12 proved L1D size drives gather latency:
// 222 KB smem -> 6 KB L1D -> 1.8x regression at identical regs/code).
// ---------------------------------------------------------------------------

#define NLEV 16
#define TSIZE (1u << 19)
#define TMASK (TSIZE - 1u)
#define PRIME1 2654435761u
#define PRIME2 805459861u

#define BLOCK 384

// shared layout (bytes)
#define WS1_OFF 0                      // W1^T fp16 [64][72]   = 9216 B
#define WS2_OFF 9216                   // W2^T fp16 [64][72]   = 9216 B
#define B1S_OFF 18432                  // b1 fp32 [64]
#define B2S_OFF (B1S_OFF + 256)
#define W3S_OFF (B2S_OFF + 256)
#define B3S_OFF (W3S_OFF + 256)
#define X_OFF   19456                  // X fp16 [384][72]; H1 ALIASES X
#define SMEM_BYTES (X_OFF + BLOCK * 72 * 2)   // 74752 B -> 2 CTAs/SM (149.5 KB)

struct Scales { float s[NLEV]; };

__device__ __forceinline__ void mma16816(float& c0, float& c1, float& c2, float& c3,
                                         unsigned a0, unsigned a1, unsigned a2, unsigned a3,
                                         unsigned b0, unsigned b1) {
    asm volatile("mma.sync.aligned.m16n8k16.row.col.f32.f16.f16.f32 "
                 "{%0,%1,%2,%3}, {%4,%5,%6,%7}, {%8,%9}, {%0,%1,%2,%3};"
                 : "+f"(c0), "+f"(c1), "+f"(c2), "+f"(c3)
                 : "r"(a0), "r"(a1), "r"(a2), "r"(a3), "r"(b0), "r"(b1));
}

__global__ __launch_bounds__(BLOCK, 2)
void sdf_kernel(const float* __restrict__ dirs,
                const float* __restrict__ table,
                const float* __restrict__ W1, const float* __restrict__ b1,
                const float* __restrict__ W2, const float* __restrict__ b2,
                const float* __restrict__ W3, const float* __restrict__ b3,
                float* __restrict__ out, int n, Scales sc)
{
    extern __shared__ __align__(16) char smem[];
    __half*  ws1h = (__half*)(smem + WS1_OFF);
    __half*  ws2h = (__half*)(smem + WS2_OFF);
    float*   b1s  = (float*)(smem + B1S_OFF);
    float*   b2s  = (float*)(smem + B2S_OFF);
    float*   w3s  = (float*)(smem + W3S_OFF);
    float*   b3s  = (float*)(smem + B3S_OFF);

    const int tid = threadIdx.x;

    // ---- stage weights (transposed, fp16) ----
    for (int i = tid; i < 64 * 72 / 2; i += BLOCK)
        ((unsigned*)ws1h)[i] = 0u;
    __syncthreads();
    for (int i = tid; i < 35 * 64; i += BLOCK) {
        int k = i >> 6, nn = i & 63;
        ws1h[nn * 72 + k] = __float2half(W1[i]);
    }
    for (int i = tid; i < 64 * 64; i += BLOCK) {
        int k = i >> 6, nn = i & 63;
        ws2h[nn * 72 + k] = __float2half(W2[i]);
    }
    if (tid < 64) {
        b1s[tid] = b1[tid];
        b2s[tid] = b2[tid];
        w3s[tid] = W3[tid];
        if (tid == 0) b3s[0] = b3[0];
    }
    __syncthreads();

    // ---- encode (one thread = one ray) ----
    const int ray  = blockIdx.x * BLOCK + tid;
    const int rayc = ray < n ? ray : (n - 1);

    const float dx = dirs[rayc * 3 + 0];
    const float dy = dirs[rayc * 3 + 1];
    const float dz = dirs[rayc * 3 + 2];
    const float x = fmaf(dx, 0.49f, 0.49f);
    const float y = fmaf(dy, 0.49f, 0.49f);
    const float z = fmaf(dz, 0.49f, 0.49f);

    __half2* Xh2 = (__half2*)(smem + X_OFF);
    const int xrow = tid * 36;

    Xh2[xrow + 0] = __floats2half2_rn(dx, dy);
    float prev = dz;

    // dense levels 0..4 (res^3 <= 2^19), unrolled from GLOBAL
    const unsigned RES[5] = {16u, 23u, 31u, 43u, 59u};
    #pragma unroll
    for (int l = 0; l < 5; l++) {
        const float s = sc.s[l];
        const float px = fmaf(x, s, 0.5f);
        const float py = fmaf(y, s, 0.5f);
        const float pz = fmaf(z, s, 0.5f);
        const float fpx = floorf(px), fpy = floorf(py), fpz = floorf(pz);
        const float fx = px - fpx, fy = py - fpy, fz = pz - fpz;
        const unsigned ix = (unsigned)fpx, iy = (unsigned)fpy, iz = (unsigned)fpz;
        const float wx = fx * fx * (3.0f - 2.0f * fx);
        const float wy = fy * fy * (3.0f - 2.0f * fy);
        const float wz = fz * fz * (3.0f - 2.0f * fz);
        const float wx0 = 1.0f - wx, wy0 = 1.0f - wy, wz0 = 1.0f - wz;

        const unsigned R = RES[l], R2 = R * R;
        const unsigned base = ix + iy * R + iz * R2;

        const float2* tl = reinterpret_cast<const float2*>(table) + (size_t)l * TSIZE;
        const float2 c0 = tl[base];           const float2 c1 = tl[base + 1u];
        const float2 c2 = tl[base + R];       const float2 c3 = tl[base + R + 1u];
        const float2 c4 = tl[base + R2];      const float2 c5 = tl[base + R2 + 1u];
        const float2 c6 = tl[base + R2 + R];  const float2 c7 = tl[base + R2 + R + 1u];

        const float w00 = wx0 * wy0, w10 = wx * wy0;
        const float w01 = wx0 * wy,  w11 = wx * wy;

        float t0 = c0.x * w00;  t0 = fmaf(c1.x, w10, t0);
        t0 = fmaf(c2.x, w01, t0); t0 = fmaf(c3.x, w11, t0);
        float t1 = c4.x * w00;  t1 = fmaf(c5.x, w10, t1);
        t1 = fmaf(c6.x, w01, t1); t1 = fmaf(c7.x, w11, t1);
        const float a0 = fmaf(t1, wz, t0 * wz0);

        float u0 = c0.y * w00;  u0 = fmaf(c1.y, w10, u0);
        u0 = fmaf(c2.y, w01, u0); u0 = fmaf(c3.y, w11, u0);
        float u1 = c4.y * w00;  u1 = fmaf(c5.y, w10, u1);
        u1 = fmaf(c6.y, w01, u1); u1 = fmaf(c7.y, w11, u1);
        const float a1 = fmaf(u1, wz, u0 * wz0);

        Xh2[xrow + l + 1] = __floats2half2_rn(prev, a0);
        prev = a1;
    }

    // hashed levels 5..15, rolled (keeps regs under the 2-CTA budget)
    #pragma unroll 1
    for (int l = 5; l < NLEV; l++) {
        const float s = sc.s[l];
        const float px = fmaf(x, s, 0.5f);
        const float py = fmaf(y, s, 0.5f);
        const float pz = fmaf(z, s, 0.5f);
        const float fpx = floorf(px), fpy = floorf(py), fpz = floorf(pz);
        const float fx = px - fpx, fy = py - fpy, fz = pz - fpz;
        const unsigned ix = (unsigned)fpx, iy = (unsigned)fpy, iz = (unsigned)fpz;
        const float wx = fx * fx * (3.0f - 2.0f * fx);
        const float wy = fy * fy * (3.0f - 2.0f * fy);
        const float wz = fz * fz * (3.0f - 2.0f * fz);
        const float wx0 = 1.0f - wx, wy0 = 1.0f - wy, wz0 = 1.0f - wz;

        const unsigned hx0 = ix,          hx1 = ix + 1u;
        const unsigned hy0 = iy * PRIME1, hy1 = hy0 + PRIME1;
        const unsigned hz0 = iz * PRIME2, hz1 = hz0 + PRIME2;
        const unsigned idx0 = (hx0 ^ hy0 ^ hz0) & TMASK;
        const unsigned idx1 = (hx1 ^ hy0 ^ hz0) & TMASK;
        const unsigned idx2 = (hx0 ^ hy1 ^ hz0) & TMASK;
        const unsigned idx3 = (hx1 ^ hy1 ^ hz0) & TMASK;
        const unsigned idx4 = (hx0 ^ hy0 ^ hz1) & TMASK;
        const unsigned idx5 = (hx1 ^ hy0 ^ hz1) & TMASK;
        const unsigned idx6 = (hx0 ^ hy1 ^ hz1) & TMASK;
        const unsigned idx7 = (hx1 ^ hy1 ^ hz1) & TMASK;

        const float2* tl = reinterpret_cast<const float2*>(table) + (size_t)l * TSIZE;
        const float2 c0 = tl[idx0], c1 = tl[idx1], c2 = tl[idx2], c3 = tl[idx3];
        const float2 c4 = tl[idx4], c5 = tl[idx5], c6 = tl[idx6], c7 = tl[idx7];

        const float w00 = wx0 * wy0, w10 = wx * wy0;
        const float w01 = wx0 * wy,  w11 = wx * wy;

        float t0 = c0.x * w00;  t0 = fmaf(c1.x, w10, t0);
        t0 = fmaf(c2.x, w01, t0); t0 = fmaf(c3.x, w11, t0);
        float t1 = c4.x * w00;  t1 = fmaf(c5.x, w10, t1);
        t1 = fmaf(c6.x, w01, t1); t1 = fmaf(c7.x, w11, t1);
        const float a0 = fmaf(t1, wz, t0 * wz0);

        float u0 = c0.y * w00;  u0 = fmaf(c1.y, w10, u0);
        u0 = fmaf(c2.y, w01, u0); u0 = fmaf(c3.y, w11, u0);
        float u1 = c4.y * w00;  u1 = fmaf(c5.y, w10, u1);
        u1 = fmaf(c6.y, w01, u1); u1 = fmaf(c7.y, w11, u1);
        const float a1 = fmaf(u1, wz, u0 * wz0);

        Xh2[xrow + l + 1] = __floats2half2_rn(prev, a0);
        prev = a1;
    }
    Xh2[xrow + 17] = __floats2half2_rn(prev, 0.0f);
    const __half2 zero2 = __floats2half2_rn(0.0f, 0.0f);
    #pragma unroll
    for (int p = 18; p < 24; p++) Xh2[xrow + p] = zero2;

    __syncwarp();

    // ---- fused MLP: one warp = 32 rays; H1 aliases X (safe: per 16-row
    // tile, all A-fragments are register-resident before the tile's writes,
    // and tiles cover disjoint rows) ----
    const int lane = tid & 31;
    const int warp = tid >> 5;
    const int g   = lane >> 2;
    const int tig = lane & 3;
    const int wbase = warp * 32;

    const unsigned* Xu  = (const unsigned*)(smem + X_OFF);
    const unsigned* W1u = (const unsigned*)ws1h;
    const unsigned* W2u = (const unsigned*)ws2h;
    __half2*        H1h = (__half2*)(smem + X_OFF);     // alias
    const unsigned* H1u = (const unsigned*)H1h;

    // ---- layer 1: [32,48] @ [48,64] ----
    #pragma unroll
    for (int mt = 0; mt < 2; mt++) {
        const int r0 = wbase + mt * 16 + g;
        unsigned a[3][4];
        #pragma unroll
        for (int kt = 0; kt < 3; kt++) {
            const int o = r0 * 36 + kt * 8 + tig;
            a[kt][0] = Xu[o];           a[kt][1] = Xu[o + 288];
            a[kt][2] = Xu[o + 4];       a[kt][3] = Xu[o + 292];
        }
        #pragma unroll
        for (int nt = 0; nt < 8; nt++) {
            float c0 = 0.f, c1 = 0.f, c2 = 0.f, c3 = 0.f;
            #pragma unroll
            for (int kt = 0; kt < 3; kt++) {
                const int bo = (nt * 8 + g) * 36 + kt * 8 + tig;
                mma16816(c0, c1, c2, c3, a[kt][0], a[kt][1], a[kt][2], a[kt][3],
                         W1u[bo], W1u[bo + 4]);
            }
            const float2 bb = *(const float2*)&b1s[nt * 8 + tig * 2];
            const int ho = r0 * 36 + nt * 4 + tig;
            H1h[ho]       = __floats2half2_rn(fmaxf(c0 + bb.x, 0.f), fmaxf(c1 + bb.y, 0.f));
            H1h[ho + 288] = __floats2half2_rn(fmaxf(c2 + bb.x, 0.f), fmaxf(c3 + bb.y, 0.f));
        }
    }
    __syncwarp();

    // ---- layer 2 + fused layer 3 ----
    const float b3v = b3s[0];
    #pragma unroll
    for (int mt = 0; mt < 2; mt++) {
        const int r0 = wbase + mt * 16 + g;
        unsigned a[4][4];
        #pragma unroll
        for (int kt = 0; kt < 4; kt++) {
            const int o = r0 * 36 + kt * 8 + tig;
            a[kt][0] = H1u[o];          a[kt][1] = H1u[o + 288];
            a[kt][2] = H1u[o + 4];      a[kt][3] = H1u[o + 292];
        }
        float p0 = 0.f, p1 = 0.f;
        #pragma unroll
        for (int nt = 0; nt < 8; nt++) {
            float c0 = 0.f, c1 = 0.f, c2 = 0.f, c3 = 0.f;
            #pragma unroll
            for (int kt = 0; kt < 4; kt++) {
                const int bo = (nt * 8 + g) * 36 + kt * 8 + tig;
                mma16816(c0, c1, c2, c3, a[kt][0], a[kt][1], a[kt][2], a[kt][3],
                         W2u[bo], W2u[bo + 4]);
            }
            const float2 bb  = *(const float2*)&b2s[nt * 8 + tig * 2];
            const float2 w3v = *(const float2*)&w3s[nt * 8 + tig * 2];
            p0 = fmaf(fmaxf(c0 + bb.x, 0.f), w3v.x, p0);
            p0 = fmaf(fmaxf(c1 + bb.y, 0.f), w3v.y, p0);
            p1 = fmaf(fmaxf(c2 + bb.x, 0.f), w3v.x, p1);
            p1 = fmaf(fmaxf(c3 + bb.y, 0.f), w3v.y, p1);
        }
        p0 += __shfl_xor_sync(0xFFFFFFFFu, p0, 1);
        p0 += __shfl_xor_sync(0xFFFFFFFFu, p0, 2);
        p1 += __shfl_xor_sync(0xFFFFFFFFu, p1, 1);
        p1 += __shfl_xor_sync(0xFFFFFFFFu, p1, 2);

        if (tig == 0) {
            const int rbase = blockIdx.x * BLOCK + wbase + mt * 16 + g;
            {
                const float xv = p0 + b3v + 1.0f;
                if (rbase < n)
                    out[rbase] = fmaxf(xv, 0.0f) + log1pf(expf(-fabsf(xv)));
            }
            {
                const float xv = p1 + b3v + 1.0f;
                if (rbase + 8 < n)
                    out[rbase + 8] = fmaxf(xv, 0.0f) + log1pf(expf(-fabsf(xv)));
            }
        }
    }
}

extern "C" void kernel_launch(void* const* d_in, const int* in_sizes, int n_in,
                              void* d_out, int out_size) {
    const float* dirs  = (const float*)d_in[0];
    const float* table = (const float*)d_in[1];
    const float* W1 = (const float*)d_in[2];
    const float* b1 = (const float*)d_in[3];
    const float* W2 = (const float*)d_in[4];
    const float* b2 = (const float*)d_in[5];
    const float* W3 = (const float*)d_in[6];
    const float* b3 = (const float*)d_in[7];
    float* out = (float*)d_out;

    const int n = in_sizes[0] / 3;

    Scales sc;
    const double PLS = exp(log(2048.0 / 16.0) / 15.0);
    for (int l = 0; l < NLEV; l++)
        sc.s[l] = (float)(16.0 * pow(PLS, (double)l) - 1.0);

    cudaFuncSetAttribute(sdf_kernel, cudaFuncAttributeMaxDynamicSharedMemorySize,
                         SMEM_BYTES);

    const int blocks = (n + BLOCK - 1) / BLOCK;
    sdf_kernel<<<blocks, BLOCK, SMEM_BYTES>>>(dirs, table, W1, b1, W2, b2, W3, b3,
                                              out, n, sc);
}